// round 3
// baseline (speedup 1.0000x reference)
#include <cuda_runtime.h>
#include <math.h>

// ---------------------------------------------------------------------------
// Problem constants
// ---------------------------------------------------------------------------
#define KD      512          // model dim D
#define KH      8            // heads
#define KDH     64           // head dim
#define KHID    2730         // int(2*512*4*2/3)
#define KB      4            // batch
#define KNS     4096         // spatial tokens
#define KNT     512          // temporal tokens
#define SROWS   (KB*KNS)     // 16384
#define TROWS   (KB*KNT)     // 2048

// ---------------------------------------------------------------------------
// Scratch (static __device__ arrays; no allocation anywhere)
// ---------------------------------------------------------------------------
__device__ float g_ln_s_q [SROWS*KD];
__device__ float g_ln_s_kv[SROWS*KD];
__device__ float g_ln_t_kv[TROWS*KD];
__device__ float g_ln_t_q [TROWS*KD];
__device__ float g_s_q    [SROWS*KD];
__device__ float g_s_kv   [TROWS*2*KD];
__device__ float g_t_q    [TROWS*KD];
__device__ float g_t_kv   [SROWS*2*KD];
__device__ float g_scores [KB*KH*KNS*KNT];   // reused for s- and t-attention
__device__ float g_attn   [SROWS*KD];
__device__ float g_t_attn [TROWS*KD];
__device__ float g_h1     [SROWS*KD];
__device__ float g_t_h1   [TROWS*KD];
__device__ float g_s_ctx  [SROWS*KD];
__device__ float g_t_ctx  [TROWS*KD];
__device__ float g_t_mean [KB*KD];
__device__ float g_hmix   [SROWS*2*KD];
__device__ float g_uv     [(size_t)SROWS*2*KHID];
__device__ float g_gate   [(size_t)SROWS*KHID];

// ---------------------------------------------------------------------------
// Packed f32x2 FMA (sm_103a FFMA2 — PTX-only, see SASS_QUICKREF)
// ---------------------------------------------------------------------------
__device__ __forceinline__ float2 ffma2(float2 a, float2 b, float2 c) {
    unsigned long long ua = *reinterpret_cast<unsigned long long*>(&a);
    unsigned long long ub = *reinterpret_cast<unsigned long long*>(&b);
    unsigned long long uc = *reinterpret_cast<unsigned long long*>(&c);
    unsigned long long ud;
    asm("fma.rn.f32x2 %0, %1, %2, %3;" : "=l"(ud) : "l"(ua), "l"(ub), "l"(uc));
    return *reinterpret_cast<float2*>(&ud);
}

// ---------------------------------------------------------------------------
// Block reductions
// ---------------------------------------------------------------------------
__device__ __forceinline__ float blockReduceSum(float v) {
    __shared__ float sh[33];
    __syncthreads();
    int lane = threadIdx.x & 31, wid = threadIdx.x >> 5;
    #pragma unroll
    for (int o = 16; o; o >>= 1) v += __shfl_xor_sync(0xffffffffu, v, o);
    if (lane == 0) sh[wid] = v;
    __syncthreads();
    if (wid == 0) {
        int nw = (int)(blockDim.x >> 5);
        float r = (lane < nw) ? sh[lane] : 0.f;
        #pragma unroll
        for (int o = 16; o; o >>= 1) r += __shfl_xor_sync(0xffffffffu, r, o);
        if (lane == 0) sh[32] = r;
    }
    __syncthreads();
    return sh[32];
}

__device__ __forceinline__ float blockReduceMax(float v) {
    __shared__ float sh[33];
    __syncthreads();
    int lane = threadIdx.x & 31, wid = threadIdx.x >> 5;
    #pragma unroll
    for (int o = 16; o; o >>= 1) v = fmaxf(v, __shfl_xor_sync(0xffffffffu, v, o));
    if (lane == 0) sh[wid] = v;
    __syncthreads();
    if (wid == 0) {
        int nw = (int)(blockDim.x >> 5);
        float r = (lane < nw) ? sh[lane] : -1e30f;
        #pragma unroll
        for (int o = 16; o; o >>= 1) r = fmaxf(r, __shfl_xor_sync(0xffffffffu, r, o));
        if (lane == 0) sh[32] = r;
    }
    __syncthreads();
    return sh[32];
}

// ---------------------------------------------------------------------------
// LayerNorm: one block (128 threads) per row, Dn in {512, 1024}
// ---------------------------------------------------------------------------
__global__ void __launch_bounds__(128)
ln_kernel(const float* __restrict__ x, const float* __restrict__ g,
          const float* __restrict__ b, float* __restrict__ y, int Dn)
{
    long row = blockIdx.x;
    const float* px = x + row * (long)Dn;
    float* py = y + row * (long)Dn;
    int tid = threadIdx.x;
    int nv = Dn >> 7;
    float v[8];
    float s = 0.f;
    for (int i = 0; i < nv; i++) { v[i] = px[tid + (i << 7)]; s += v[i]; }
    s = blockReduceSum(s);
    float mean = s / (float)Dn;
    float q = 0.f;
    for (int i = 0; i < nv; i++) { float d = v[i] - mean; q += d * d; }
    q = blockReduceSum(q);
    float inv = rsqrtf(q / (float)Dn + 1e-5f);
    for (int i = 0; i < nv; i++) {
        int c = tid + (i << 7);
        py[c] = (v[i] - mean) * inv * g[c] + b[c];
    }
}

// Mix LN: row of [s_ctx(512) | t_mean(512)], Dn = 1024
__global__ void __launch_bounds__(128)
mix_ln_kernel(const float* __restrict__ s_ctx, const float* __restrict__ t_mean,
              const float* __restrict__ g, const float* __restrict__ b,
              float* __restrict__ h)
{
    int row = blockIdx.x;               // 0..16383
    int bb  = row >> 12;                // /4096
    const float* ps = s_ctx + (long)row * KD;
    const float* pm = t_mean + (long)bb * KD;
    float* py = h + (long)row * (2 * KD);
    int tid = threadIdx.x;
    float v[8];
    float s = 0.f;
    #pragma unroll
    for (int i = 0; i < 8; i++) {
        int c = tid + (i << 7);
        v[i] = (c < KD) ? ps[c] : pm[c - KD];
        s += v[i];
    }
    s = blockReduceSum(s);
    float mean = s / 1024.f;
    float q = 0.f;
    #pragma unroll
    for (int i = 0; i < 8; i++) { float d = v[i] - mean; q += d * d; }
    q = blockReduceSum(q);
    float inv = rsqrtf(q / 1024.f + 1e-5f);
    #pragma unroll
    for (int i = 0; i < 8; i++) {
        int c = tid + (i << 7);
        py[c] = (v[i] - mean) * inv * g[c] + b[c];
    }
}

// ---------------------------------------------------------------------------
// Row softmax (in place). cols multiple of 256 (512 or 4096). 256 threads.
// ---------------------------------------------------------------------------
__global__ void __launch_bounds__(256)
softmax_kernel(float* __restrict__ S, int cols)
{
    long row = blockIdx.x;
    float* p = S + row * (long)cols;
    int tid = threadIdx.x;
    int nv = cols >> 8;
    float v[16];
    float mx = -1e30f;
    for (int i = 0; i < nv; i++) { v[i] = p[tid + (i << 8)]; mx = fmaxf(mx, v[i]); }
    mx = blockReduceMax(mx);
    float s = 0.f;
    for (int i = 0; i < nv; i++) { v[i] = expf(v[i] - mx); s += v[i]; }
    s = blockReduceSum(s);
    float inv = 1.f / s;
    for (int i = 0; i < nv; i++) p[tid + (i << 8)] = v[i] * inv;
}

// ---------------------------------------------------------------------------
// t_mean: out[b][d] = mean over 512 tokens of t_ctx
// ---------------------------------------------------------------------------
__global__ void tmean_kernel(const float* __restrict__ t_ctx, float* __restrict__ out)
{
    int idx = blockIdx.x * blockDim.x + threadIdx.x;
    if (idx >= KB * KD) return;
    int bb = idx >> 9, dd = idx & 511;
    const float* p = t_ctx + (long)bb * KNT * KD + dd;
    float s = 0.f;
    for (int t = 0; t < KNT; t++) s += p[t * KD];
    out[idx] = s * (1.f / (float)KNT);
}

// ---------------------------------------------------------------------------
// SiLU gate: g = silu(u) * v,  u = uv[:, :HID], v = uv[:, HID:]
// ---------------------------------------------------------------------------
__global__ void gate_kernel(const float* __restrict__ uv, float* __restrict__ gout)
{
    long idx = (long)blockIdx.x * blockDim.x + threadIdx.x;
    const long total = (long)SROWS * KHID;
    if (idx >= total) return;
    long rowc = idx / KHID;
    int  col  = (int)(idx - rowc * KHID);
    float u  = uv[rowc * (2 * KHID) + col];
    float vv = uv[rowc * (2 * KHID) + KHID + col];
    gout[idx] = (u / (1.f + expf(-u))) * vv;
}

// ---------------------------------------------------------------------------
// GEMM NT: C[m,n] = alpha * sum_k A[m,k] * B[n,k]  (+ bias[n]) (+ Res[m,n])
// 128x128x8 tile, 256 threads, 8x8 per thread via f32x2.
// Batched over blockIdx.z with (b,h)-style offsets: z -> (z/Hn, z%Hn).
// ---------------------------------------------------------------------------
__global__ void __launch_bounds__(256)
gemm_nt(const float* __restrict__ A, const float* __restrict__ B,
        const float* __restrict__ bias, const float* __restrict__ Res,
        float* __restrict__ C,
        int M, int N, int K, int lda, int ldb, int ldc,
        int Hn, long sAb, long sAh, long sBb, long sBh, long sCb, long sCh,
        float alpha)
{
    int z = blockIdx.z;
    int zb = z / Hn, zh = z % Hn;
    A += zb * sAb + zh * sAh;
    B += zb * sBb + zh * sBh;
    C += zb * sCb + zh * sCh;
    if (Res) Res += zb * sCb + zh * sCh;

    __shared__ float As[8][128];
    __shared__ float Bs[8][128];

    int tid = threadIdx.x;
    int tx = tid & 15;      // N direction (8 cols each)
    int ty = tid >> 4;      // M direction (8 rows each)
    int row0 = blockIdx.y * 128;
    int col0 = blockIdx.x * 128;

    float2 acc[8][4];
    #pragma unroll
    for (int i = 0; i < 8; i++)
        #pragma unroll
        for (int j = 0; j < 4; j++) acc[i][j] = make_float2(0.f, 0.f);

    int lrow = tid >> 1;            // 0..127
    int lcol = (tid & 1) * 4;       // 0 or 4
    bool a4 = ((lda & 3) == 0);
    bool b4 = ((ldb & 3) == 0);

    for (int k0 = 0; k0 < K; k0 += 8) {
        // ---- A tile (transposed into As[k][m]) ----
        {
            float vx = 0.f, vy = 0.f, vz = 0.f, vw = 0.f;
            int gr = row0 + lrow;
            int kbase = k0 + lcol;
            if (gr < M) {
                if (a4 && kbase + 3 < K) {
                    float4 v = *reinterpret_cast<const float4*>(A + (long)gr * lda + kbase);
                    vx = v.x; vy = v.y; vz = v.z; vw = v.w;
                } else {
                    const float* pa = A + (long)gr * lda;
                    if (kbase + 0 < K) vx = pa[kbase + 0];
                    if (kbase + 1 < K) vy = pa[kbase + 1];
                    if (kbase + 2 < K) vz = pa[kbase + 2];
                    if (kbase + 3 < K) vw = pa[kbase + 3];
                }
            }
            As[lcol + 0][lrow] = vx; As[lcol + 1][lrow] = vy;
            As[lcol + 2][lrow] = vz; As[lcol + 3][lrow] = vw;
        }
        // ---- B tile (transposed into Bs[k][n]) ----
        {
            float vx = 0.f, vy = 0.f, vz = 0.f, vw = 0.f;
            int gn = col0 + lrow;
            int kbase = k0 + lcol;
            if (gn < N) {
                if (b4 && kbase + 3 < K) {
                    float4 v = *reinterpret_cast<const float4*>(B + (long)gn * ldb + kbase);
                    vx = v.x; vy = v.y; vz = v.z; vw = v.w;
                } else {
                    const float* pb = B + (long)gn * ldb;
                    if (kbase + 0 < K) vx = pb[kbase + 0];
                    if (kbase + 1 < K) vy = pb[kbase + 1];
                    if (kbase + 2 < K) vz = pb[kbase + 2];
                    if (kbase + 3 < K) vw = pb[kbase + 3];
                }
            }
            Bs[lcol + 0][lrow] = vx; Bs[lcol + 1][lrow] = vy;
            Bs[lcol + 2][lrow] = vz; Bs[lcol + 3][lrow] = vw;
        }
        __syncthreads();

        #pragma unroll
        for (int kk = 0; kk < 8; kk++) {
            float4 a0 = *reinterpret_cast<const float4*>(&As[kk][ty * 8]);
            float4 a1 = *reinterpret_cast<const float4*>(&As[kk][ty * 8 + 4]);
            float4 b0 = *reinterpret_cast<const float4*>(&Bs[kk][tx * 8]);
            float4 b1 = *reinterpret_cast<const float4*>(&Bs[kk][tx * 8 + 4]);
            float av[8] = {a0.x, a0.y, a0.z, a0.w, a1.x, a1.y, a1.z, a1.w};
            float2 bv[4] = {make_float2(b0.x, b0.y), make_float2(b0.z, b0.w),
                            make_float2(b1.x, b1.y), make_float2(b1.z, b1.w)};
            #pragma unroll
            for (int i = 0; i < 8; i++) {
                float2 ai = make_float2(av[i], av[i]);
                #pragma unroll
                for (int j = 0; j < 4; j++) acc[i][j] = ffma2(ai, bv[j], acc[i][j]);
            }
        }
        __syncthreads();
    }

    // ---- epilogue ----
    #pragma unroll
    for (int i = 0; i < 8; i++) {
        int gm = row0 + ty * 8 + i;
        if (gm >= M) continue;
        #pragma unroll
        for (int j = 0; j < 4; j++) {
            int gn0 = col0 + tx * 8 + j * 2;
            float vals[2] = {acc[i][j].x, acc[i][j].y};
            #pragma unroll
            for (int l = 0; l < 2; l++) {
                int n = gn0 + l;
                if (n < N) {
                    float v = vals[l] * alpha;
                    if (bias) v += bias[n];
                    if (Res)  v += Res[(long)gm * ldc + n];
                    C[(long)gm * ldc + n] = v;
                }
            }
        }
    }
}

// ---------------------------------------------------------------------------
// GEMM NN: C[m,n] = sum_k A[m,k] * B[k,n]   (attn @ V). 128x64x8 tile.
// ---------------------------------------------------------------------------
__global__ void __launch_bounds__(256)
gemm_nn(const float* __restrict__ A, const float* __restrict__ B,
        float* __restrict__ C,
        int M, int N, int K, int lda, int ldb, int ldc,
        int Hn, long sAb, long sAh, long sBb, long sBh, long sCb, long sCh)
{
    int z = blockIdx.z;
    int zb = z / Hn, zh = z % Hn;
    A += zb * sAb + zh * sAh;
    B += zb * sBb + zh * sBh;
    C += zb * sCb + zh * sCh;

    __shared__ float As[8][128];
    __shared__ float Bs[8][64];

    int tid = threadIdx.x;
    int tx = tid & 15;      // N direction, 4 cols each
    int ty = tid >> 4;      // M direction, 8 rows each
    int row0 = blockIdx.y * 128;
    int col0 = blockIdx.x * 64;

    float2 acc[8][2];
    #pragma unroll
    for (int i = 0; i < 8; i++) { acc[i][0] = make_float2(0.f, 0.f); acc[i][1] = make_float2(0.f, 0.f); }

    int lrow = tid >> 1;
    int lcol = (tid & 1) * 4;
    int brow = tid >> 5;            // 0..7 (k)
    int bcol = (tid & 31) * 2;      // 0..62 (n)

    for (int k0 = 0; k0 < K; k0 += 8) {
        // A tile
        {
            float vx = 0.f, vy = 0.f, vz = 0.f, vw = 0.f;
            int gr = row0 + lrow;
            int kbase = k0 + lcol;
            if (gr < M && kbase + 3 < K) {
                float4 v = *reinterpret_cast<const float4*>(A + (long)gr * lda + kbase);
                vx = v.x; vy = v.y; vz = v.z; vw = v.w;
            } else if (gr < M) {
                const float* pa = A + (long)gr * lda;
                if (kbase + 0 < K) vx = pa[kbase + 0];
                if (kbase + 1 < K) vy = pa[kbase + 1];
                if (kbase + 2 < K) vz = pa[kbase + 2];
                if (kbase + 3 < K) vw = pa[kbase + 3];
            }
            As[lcol + 0][lrow] = vx; As[lcol + 1][lrow] = vy;
            As[lcol + 2][lrow] = vz; As[lcol + 3][lrow] = vw;
        }
        // B tile (natural layout)
        {
            float2 bv = make_float2(0.f, 0.f);
            int gk = k0 + brow;
            int gn = col0 + bcol;
            if (gk < K && gn + 1 < N)
                bv = *reinterpret_cast<const float2*>(B + (long)gk * ldb + gn);
            *reinterpret_cast<float2*>(&Bs[brow][bcol]) = bv;
        }
        __syncthreads();

        #pragma unroll
        for (int kk = 0; kk < 8; kk++) {
            float4 a0 = *reinterpret_cast<const float4*>(&As[kk][ty * 8]);
            float4 a1 = *reinterpret_cast<const float4*>(&As[kk][ty * 8 + 4]);
            float4 bq = *reinterpret_cast<const float4*>(&Bs[kk][tx * 4]);
            float av[8] = {a0.x, a0.y, a0.z, a0.w, a1.x, a1.y, a1.z, a1.w};
            float2 bv0 = make_float2(bq.x, bq.y);
            float2 bv1 = make_float2(bq.z, bq.w);
            #pragma unroll
            for (int i = 0; i < 8; i++) {
                float2 ai = make_float2(av[i], av[i]);
                acc[i][0] = ffma2(ai, bv0, acc[i][0]);
                acc[i][1] = ffma2(ai, bv1, acc[i][1]);
            }
        }
        __syncthreads();
    }

    #pragma unroll
    for (int i = 0; i < 8; i++) {
        int gm = row0 + ty * 8 + i;
        if (gm >= M) continue;
        float* pc = C + (long)gm * ldc + col0 + tx * 4;
        int gn = col0 + tx * 4;
        if (gn + 3 < N) {
            pc[0] = acc[i][0].x; pc[1] = acc[i][0].y;
            pc[2] = acc[i][1].x; pc[3] = acc[i][1].y;
        } else {
            if (gn + 0 < N) pc[0] = acc[i][0].x;
            if (gn + 1 < N) pc[1] = acc[i][0].y;
            if (gn + 2 < N) pc[2] = acc[i][1].x;
            if (gn + 3 < N) pc[3] = acc[i][1].y;
        }
    }
}

// ---------------------------------------------------------------------------
// Host-side launch helpers
// ---------------------------------------------------------------------------
static inline void launch_nt(const float* A, const float* B, const float* bias,
                             const float* res, float* C,
                             int M, int N, int K, int lda, int ldb, int ldc,
                             int Z, int Hn,
                             long sAb, long sAh, long sBb, long sBh,
                             long sCb, long sCh, float alpha)
{
    dim3 grid((N + 127) / 128, (M + 127) / 128, Z);
    gemm_nt<<<grid, 256>>>(A, B, bias, res, C, M, N, K, lda, ldb, ldc,
                           Hn, sAb, sAh, sBb, sBh, sCb, sCh, alpha);
}

static inline void launch_nn(const float* A, const float* B, float* C,
                             int M, int N, int K, int lda, int ldb, int ldc,
                             int Z, int Hn,
                             long sAb, long sAh, long sBb, long sBh,
                             long sCb, long sCh)
{
    dim3 grid((N + 63) / 64, (M + 127) / 128, Z);
    gemm_nn<<<grid, 256>>>(A, B, C, M, N, K, lda, ldb, ldc,
                           Hn, sAb, sAh, sBb, sBh, sCb, sCh);
}

extern "C" void kernel_launch(void* const* d_in, const int* in_sizes, int n_in,
                              void* d_out, int out_size)
{
    (void)in_sizes; (void)n_in; (void)out_size;

    const float* spatial   = (const float*)d_in[0];
    const float* temporal  = (const float*)d_in[1];
    const float* s_ln_q_g  = (const float*)d_in[2];
    const float* s_ln_q_b  = (const float*)d_in[3];
    const float* s_ln_kv_g = (const float*)d_in[4];
    const float* s_ln_kv_b = (const float*)d_in[5];
    const float* s_Wqkv    = (const float*)d_in[6];
    const float* s_bqkv    = (const float*)d_in[7];
    const float* s_Wo      = (const float*)d_in[8];
    const float* s_bo      = (const float*)d_in[9];
    const float* s_Wp      = (const float*)d_in[10];
    const float* s_bp      = (const float*)d_in[11];
    const float* t_ln_q_g  = (const float*)d_in[12];
    const float* t_ln_q_b  = (const float*)d_in[13];
    const float* t_ln_kv_g = (const float*)d_in[14];
    const float* t_ln_kv_b = (const float*)d_in[15];
    const float* t_Wqkv    = (const float*)d_in[16];
    const float* t_bqkv    = (const float*)d_in[17];
    const float* t_Wo      = (const float*)d_in[18];
    const float* t_bo      = (const float*)d_in[19];
    const float* t_Wp      = (const float*)d_in[20];
    const float* t_bp      = (const float*)d_in[21];
    const float* mix_ln_g  = (const float*)d_in[22];
    const float* mix_ln_b  = (const float*)d_in[23];
    const float* mix_Win   = (const float*)d_in[24];
    const float* mix_bin   = (const float*)d_in[25];
    const float* mix_Wout  = (const float*)d_in[26];
    const float* mix_bout  = (const float*)d_in[27];
    float* out = (float*)d_out;

    void* p;
    cudaGetSymbolAddress(&p, g_ln_s_q);  float* ln_s_q  = (float*)p;
    cudaGetSymbolAddress(&p, g_ln_s_kv); float* ln_s_kv = (float*)p;
    cudaGetSymbolAddress(&p, g_ln_t_kv); float* ln_t_kv = (float*)p;
    cudaGetSymbolAddress(&p, g_ln_t_q);  float* ln_t_q  = (float*)p;
    cudaGetSymbolAddress(&p, g_s_q);     float* s_q     = (float*)p;
    cudaGetSymbolAddress(&p, g_s_kv);    float* s_kv    = (float*)p;
    cudaGetSymbolAddress(&p, g_t_q);     float* t_q     = (float*)p;
    cudaGetSymbolAddress(&p, g_t_kv);    float* t_kv    = (float*)p;
    cudaGetSymbolAddress(&p, g_scores);  float* scores  = (float*)p;
    cudaGetSymbolAddress(&p, g_attn);    float* s_attn  = (float*)p;
    cudaGetSymbolAddress(&p, g_t_attn);  float* t_attn  = (float*)p;
    cudaGetSymbolAddress(&p, g_h1);      float* s_h1    = (float*)p;
    cudaGetSymbolAddress(&p, g_t_h1);    float* t_h1    = (float*)p;
    cudaGetSymbolAddress(&p, g_s_ctx);   float* s_ctx   = (float*)p;
    cudaGetSymbolAddress(&p, g_t_ctx);   float* t_ctx   = (float*)p;
    cudaGetSymbolAddress(&p, g_t_mean);  float* t_mean  = (float*)p;
    cudaGetSymbolAddress(&p, g_hmix);    float* hmix    = (float*)p;
    cudaGetSymbolAddress(&p, g_uv);      float* uv      = (float*)p;
    cudaGetSymbolAddress(&p, g_gate);    float* gate    = (float*)p;

    const float sc = 0.125f;  // 1/sqrt(64)

    // ---- LayerNorms ----
    ln_kernel<<<SROWS, 128>>>(spatial,  s_ln_q_g,  s_ln_q_b,  ln_s_q,  KD);
    ln_kernel<<<TROWS, 128>>>(temporal, s_ln_kv_g, s_ln_kv_b, ln_t_kv, KD);
    ln_kernel<<<TROWS, 128>>>(temporal, t_ln_q_g,  t_ln_q_b,  ln_t_q,  KD);
    ln_kernel<<<SROWS, 128>>>(spatial,  t_ln_kv_g, t_ln_kv_b, ln_s_kv, KD);

    // ---- Projections ----
    launch_nt(ln_s_q,  s_Wqkv,           s_bqkv,      nullptr, s_q,
              SROWS, KD, KD, KD, KD, KD, 1, 1, 0,0,0,0,0,0, 1.f);
    launch_nt(ln_t_kv, s_Wqkv + KD*KD,   s_bqkv + KD, nullptr, s_kv,
              TROWS, 2*KD, KD, KD, KD, 2*KD, 1, 1, 0,0,0,0,0,0, 1.f);
    launch_nt(ln_t_q,  t_Wqkv,           t_bqkv,      nullptr, t_q,
              TROWS, KD, KD, KD, KD, KD, 1, 1, 0,0,0,0,0,0, 1.f);
    launch_nt(ln_s_kv, t_Wqkv + KD*KD,   t_bqkv + KD, nullptr, t_kv,
              SROWS, 2*KD, KD, KD, KD, 2*KD, 1, 1, 0,0,0,0,0,0, 1.f);

    // ---- Spatial attention (q: spatial, kv: temporal) ----
    launch_nt(s_q, s_kv, nullptr, nullptr, scores,
              KNS, KNT, KDH, KD, 2*KD, KNT,
              KB*KH, KH,
              (long)KNS*KD, KDH,            // A: b, h offsets
              (long)KNT*2*KD, KDH,          // B(k): b, h offsets
              (long)KH*KNS*KNT, (long)KNS*KNT,
              sc);
    softmax_kernel<<<KB*KH*KNS, 256>>>(scores, KNT);
    launch_nn(scores, s_kv + KD, s_attn,
              KNS, KDH, KNT, KNT, 2*KD, KD,
              KB*KH, KH,
              (long)KH*KNS*KNT, (long)KNS*KNT,
              (long)KNT*2*KD, KDH,
              (long)KNS*KD, KDH);
    launch_nt(s_attn, s_Wo, s_bo, nullptr, s_h1,
              SROWS, KD, KD, KD, KD, KD, 1, 1, 0,0,0,0,0,0, 1.f);
    launch_nt(s_h1, s_Wp, s_bp, spatial, s_ctx,
              SROWS, KD, KD, KD, KD, KD, 1, 1, 0,0,0,0,0,0, 1.f);

    // ---- Temporal attention (q: temporal, kv: spatial) ----
    launch_nt(t_q, t_kv, nullptr, nullptr, scores,
              KNT, KNS, KDH, KD, 2*KD, KNS,
              KB*KH, KH,
              (long)KNT*KD, KDH,
              (long)KNS*2*KD, KDH,
              (long)KH*KNT*KNS, (long)KNT*KNS,
              sc);
    softmax_kernel<<<KB*KH*KNT, 256>>>(scores, KNS);
    launch_nn(scores, t_kv + KD, t_attn,
              KNT, KDH, KNS, KNS, 2*KD, KD,
              KB*KH, KH,
              (long)KH*KNT*KNS, (long)KNT*KNS,
              (long)KNS*2*KD, KDH,
              (long)KNT*KD, KDH);
    launch_nt(t_attn, t_Wo, t_bo, nullptr, t_h1,
              TROWS, KD, KD, KD, KD, KD, 1, 1, 0,0,0,0,0,0, 1.f);
    launch_nt(t_h1, t_Wp, t_bp, temporal, t_ctx,
              TROWS, KD, KD, KD, KD, KD, 1, 1, 0,0,0,0,0,0, 1.f);

    // ---- Mix ----
    tmean_kernel<<<(KB*KD + 127) / 128, 128>>>(t_ctx, t_mean);
    mix_ln_kernel<<<SROWS, 128>>>(s_ctx, t_mean, mix_ln_g, mix_ln_b, hmix);

    launch_nt(hmix, mix_Win, mix_bin, nullptr, uv,
              SROWS, 2*KHID, 2*KD, 2*KD, 2*KD, 2*KHID, 1, 1, 0,0,0,0,0,0, 1.f);

    {
        long total = (long)SROWS * KHID;
        int blocks = (int)((total + 255) / 256);
        gate_kernel<<<blocks, 256>>>(uv, gate);
    }

    launch_nt(gate, mix_Wout, mix_bout, s_ctx, out,
              SROWS, KD, KHID, KHID, KHID, KD, 1, 1, 0,0,0,0,0,0, 1.f);
}

// round 5
// speedup vs baseline: 2.3835x; 2.3835x over previous
#include <cuda_runtime.h>
#include <cuda_bf16.h>
#include <math.h>
#include <stdint.h>

#define KD    512
#define KH    8
#define KDH   64
#define KHID  2730
#define KB    4
#define KNS   4096
#define KNT   512
#define SROWS (KB*KNS)
#define TROWS (KB*KNT)
#define KPAD  2752
#define NPAD  5504

typedef __nv_bfloat16 bf;
#define DEVB(n, s) __device__ __align__(16) bf n[s]
#define DEVF(n, s) __device__ __align__(16) float n[s]

// activations / intermediates
DEVB(LsQh,SROWS*KD); DEVB(LsQl,SROWS*KD);
DEVB(LtKVh,TROWS*KD);DEVB(LtKVl,TROWS*KD);
DEVB(LtQh,TROWS*KD); DEVB(LtQl,TROWS*KD);
DEVB(LsKVh,SROWS*KD);DEVB(LsKVl,SROWS*KD);
DEVB(Qsh,SROWS*KD);  DEVB(Qsl,SROWS*KD);
DEVB(Ksh,TROWS*KD);  DEVB(Ksl,TROWS*KD);
DEVB(VtSh,KB*KD*KNT);DEVB(VtSl,KB*KD*KNT);
DEVB(Qth,TROWS*KD);  DEVB(Qtl,TROWS*KD);
DEVB(Kth,SROWS*KD);  DEVB(Ktl,SROWS*KD);
DEVB(VtTh,KB*KD*KNS);DEVB(VtTl,KB*KD*KNS);
DEVF(Sc,(size_t)KB*KH*KNS*KNT);
DEVB(Pph,(size_t)KB*KH*KNS*KNT); DEVB(Ppl,(size_t)KB*KH*KNS*KNT);
DEVB(AtSh,SROWS*KD); DEVB(AtSl,SROWS*KD);
DEVB(AtTh,TROWS*KD); DEVB(AtTl,TROWS*KD);
DEVB(H1Sh,SROWS*KD); DEVB(H1Sl,SROWS*KD);
DEVB(H1Th,TROWS*KD); DEVB(H1Tl,TROWS*KD);
DEVF(SctxF,SROWS*KD);
DEVF(TctxF,TROWS*KD);
DEVF(TmeanF,KB*KD);
DEVB(Hmh,SROWS*2*KD); DEVB(Hml,SROWS*2*KD);
DEVF(UvF,(size_t)SROWS*NPAD);
DEVB(Gth,(size_t)SROWS*KPAD); DEVB(Gtl,(size_t)SROWS*KPAD);
// weights
DEVB(WqkvSh,3*KD*KD); DEVB(WqkvSl,3*KD*KD);
DEVB(WqkvTh,3*KD*KD); DEVB(WqkvTl,3*KD*KD);
DEVB(WoSh,KD*KD); DEVB(WoSl,KD*KD);
DEVB(WpSh,KD*KD); DEVB(WpSl,KD*KD);
DEVB(WoTh,KD*KD); DEVB(WoTl,KD*KD);
DEVB(WpTh,KD*KD); DEVB(WpTl,KD*KD);
DEVB(Winh,NPAD*2*KD); DEVB(Winl,NPAD*2*KD);
DEVB(Wouth,KD*KPAD);  DEVB(Woutl,KD*KPAD);
DEVF(BinP,NPAD);

__device__ __forceinline__ void splitw(float x, bf* H, bf* L){
    bf h = __float2bfloat16(x); *H = h; *L = __float2bfloat16(x - __bfloat162float(h));
}

__device__ __forceinline__ void mma_bf(float* c, const uint32_t* a, const uint32_t* b){
    asm volatile("mma.sync.aligned.m16n8k16.row.col.f32.bf16.bf16.f32 "
        "{%0,%1,%2,%3}, {%4,%5,%6,%7}, {%8,%9}, {%0,%1,%2,%3};"
        : "+f"(c[0]),"+f"(c[1]),"+f"(c[2]),"+f"(c[3])
        : "r"(a[0]),"r"(a[1]),"r"(a[2]),"r"(a[3]), "r"(b[0]),"r"(b[1]));
}

// ---------------- reductions ----------------
__device__ __forceinline__ float brSum(float v){
    __shared__ float sh[33]; __syncthreads();
    int ln = threadIdx.x&31, w = threadIdx.x>>5;
    #pragma unroll
    for(int o=16;o;o>>=1) v += __shfl_xor_sync(~0u,v,o);
    if(!ln) sh[w]=v; __syncthreads();
    if(!w){ int nw=blockDim.x>>5; float r=(ln<nw)?sh[ln]:0.f;
        #pragma unroll
        for(int o=16;o;o>>=1) r += __shfl_xor_sync(~0u,r,o);
        if(!ln) sh[32]=r; }
    __syncthreads(); return sh[32];
}
__device__ __forceinline__ float brMax(float v){
    __shared__ float sh[33]; __syncthreads();
    int ln = threadIdx.x&31, w = threadIdx.x>>5;
    #pragma unroll
    for(int o=16;o;o>>=1) v = fmaxf(v,__shfl_xor_sync(~0u,v,o));
    if(!ln) sh[w]=v; __syncthreads();
    if(!w){ int nw=blockDim.x>>5; float r=(ln<nw)?sh[ln]:-1e30f;
        #pragma unroll
        for(int o=16;o;o>>=1) r = fmaxf(r,__shfl_xor_sync(~0u,r,o));
        if(!ln) sh[32]=r; }
    __syncthreads(); return sh[32];
}

// ---------------- elementwise kernels ----------------
__global__ void __launch_bounds__(128)
ln_k(const float* __restrict__ x, const float* __restrict__ g, const float* __restrict__ b,
     bf* __restrict__ yh, bf* __restrict__ yl)
{
    long row = blockIdx.x;
    const float* px = x + row*KD;
    bf *ph = yh + row*KD, *pl = yl + row*KD;
    int t = threadIdx.x;
    float v[4]; float s=0.f;
    #pragma unroll
    for(int i=0;i<4;i++){ v[i]=px[t+(i<<7)]; s+=v[i]; }
    s = brSum(s); float m = s*(1.f/KD);
    float q=0.f;
    #pragma unroll
    for(int i=0;i<4;i++){ float d=v[i]-m; q+=d*d; }
    q = brSum(q); float inv = rsqrtf(q*(1.f/KD)+1e-5f);
    #pragma unroll
    for(int i=0;i<4;i++){ int c=t+(i<<7); splitw((v[i]-m)*inv*g[c]+b[c], ph+c, pl+c); }
}

__global__ void __launch_bounds__(128)
mixln_k(const float* __restrict__ sc, const float* __restrict__ tm,
        const float* __restrict__ g, const float* __restrict__ b,
        bf* __restrict__ yh, bf* __restrict__ yl)
{
    int row = blockIdx.x, bb = row>>12;
    const float *ps = sc + (long)row*KD, *pm = tm + (long)bb*KD;
    bf *ph = yh + (long)row*2*KD, *pl = yl + (long)row*2*KD;
    int t = threadIdx.x;
    float v[8]; float s=0.f;
    #pragma unroll
    for(int i=0;i<8;i++){ int c=t+(i<<7); v[i]=(c<KD)?ps[c]:pm[c-KD]; s+=v[i]; }
    s = brSum(s); float m = s*(1.f/1024.f);
    float q=0.f;
    #pragma unroll
    for(int i=0;i<8;i++){ float d=v[i]-m; q+=d*d; }
    q = brSum(q); float inv = rsqrtf(q*(1.f/1024.f)+1e-5f);
    #pragma unroll
    for(int i=0;i<8;i++){ int c=t+(i<<7); splitw((v[i]-m)*inv*g[c]+b[c], ph+c, pl+c); }
}

template<int NV>
__global__ void __launch_bounds__(256)
sm_k(const float* __restrict__ S, bf* __restrict__ Ph, bf* __restrict__ Pl)
{
    long row = blockIdx.x;
    const int cols = NV*256;
    const float* p = S + row*(long)cols;
    bf *ph = Ph + row*(long)cols, *pl = Pl + row*(long)cols;
    int t = threadIdx.x;
    float v[NV]; float mx=-1e30f;
    #pragma unroll
    for(int i=0;i<NV;i++){ v[i]=p[t+(i<<8)]; mx=fmaxf(mx,v[i]); }
    mx = brMax(mx);
    float s=0.f;
    #pragma unroll
    for(int i=0;i<NV;i++){ v[i]=__expf(v[i]-mx); s+=v[i]; }
    s = brSum(s); float inv = 1.f/s;
    #pragma unroll
    for(int i=0;i<NV;i++){ int c=t+(i<<8); splitw(v[i]*inv, ph+c, pl+c); }
}

__global__ void tmean_k(const float* __restrict__ tc, float* __restrict__ o)
{
    int i = blockIdx.x*blockDim.x + threadIdx.x;
    if(i >= KB*KD) return;
    int bb=i>>9, dd=i&511;
    const float* p = tc + (long)bb*KNT*KD + dd;
    float s=0.f;
    for(int t=0;t<KNT;t++) s += p[t*KD];
    o[i] = s*(1.f/KNT);
}

__global__ void gate_k(const float* __restrict__ uv, bf* __restrict__ gh, bf* __restrict__ gl)
{
    long i = (long)blockIdx.x*blockDim.x + threadIdx.x;
    if(i >= (long)SROWS*KPAD) return;
    long r = i/KPAD; int c = (int)(i - r*KPAD);
    float val = 0.f;
    if(c < KHID){
        float u = uv[r*NPAD + c], vv = uv[r*NPAD + KHID + c];
        val = (u/(1.f+__expf(-u)))*vv;
    }
    splitw(val, gh+i, gl+i);
}

__global__ void conv_k(const float* __restrict__ s, bf* __restrict__ dh, bf* __restrict__ dl,
                       int dR, int dC, int sR, int sC)
{
    long i = (long)blockIdx.x*blockDim.x + threadIdx.x;
    if(i >= (long)dR*dC) return;
    int r = (int)(i/dC), c = (int)(i - (long)r*dC);
    float v = (r<sR && c<sC) ? s[(long)r*sC + c] : 0.f;
    splitw(v, dh+i, dl+i);
}

__global__ void padc_k(const float* __restrict__ s, float* __restrict__ d, int ns, int nd)
{
    int i = blockIdx.x*blockDim.x + threadIdx.x;
    if(i<nd) d[i] = (i<ns)?s[i]:0.f;
}

// ---------------- split-bf16 HMMA GEMM (NT) ----------------
// C[m,n] = alpha*sum_k A[m,k]*B[n,k] (+bias)(+Res). M%128==0, N%BN==0, K%32==0.
// 256 threads = 8 warps in 2(M) x 4(N); per-warp 64 x BN/4 via m16n8k16 bf16.
template<int BN>
__global__ void __launch_bounds__(256)
gemm_mma(const bf* __restrict__ Ah, const bf* __restrict__ Al,
         const bf* __restrict__ Bh, const bf* __restrict__ Bl,
         const float* __restrict__ bias, int biasMode, const float* __restrict__ Res,
         float* __restrict__ Cf, bf* __restrict__ Ch, bf* __restrict__ Cl,
         int K, int lda, int ldb, int ldc,
         int Hn, long sAb, long sAh2, long sBb, long sBh2, long sCb, long sCh2,
         float alpha)
{
    extern __shared__ bf sm[];
    bf* sA_h = sm;                    // [128][40]
    bf* sA_l = sm + 5120;
    bf* sB_h = sm + 10240;            // [BN][40]
    bf* sB_l = sm + 10240 + BN*40;

    const int tid = threadIdx.x, lane = tid&31, w = tid>>5;
    const int wm = w&1, wn = w>>1;
    const int gid = lane>>2, t4 = lane&3;
    constexpr int NT = BN/32;         // n8 tiles per warp
    constexpr int BW = BN*4/256;      // B 16B-words per thread

    int z = blockIdx.z, zb = z/Hn, zh = z - zb*Hn;
    long coff = (long)zb*sCb + (long)zh*sCh2;
    Ah += (long)zb*sAb + (long)zh*sAh2; Al += (long)zb*sAb + (long)zh*sAh2;
    Bh += (long)zb*sBb + (long)zh*sBh2; Bl += (long)zb*sBb + (long)zh*sBh2;

    const int row0 = blockIdx.y << 7;
    const int col0 = blockIdx.x * BN;

    float cc[4][NT][4];
    #pragma unroll
    for(int i=0;i<4;i++)
        #pragma unroll
        for(int j=0;j<NT;j++)
            #pragma unroll
            for(int q=0;q<4;q++) cc[i][j][q]=0.f;

    uint4 pAh[2], pAl[2], pBh[BW], pBl[BW];
    int nch = K >> 5;

    // prefetch chunk 0
    {
        int k0 = 0;
        #pragma unroll
        for(int i=0;i<2;i++){
            int wd = tid + (i<<8); int r = wd>>2, wi = wd&3;
            long ga = (long)(row0+r)*lda + k0 + (wi<<3);
            pAh[i] = *(const uint4*)(Ah+ga);
            pAl[i] = *(const uint4*)(Al+ga);
        }
        #pragma unroll
        for(int i=0;i<BW;i++){
            int wd = tid + (i<<8); int r = wd>>2, wi = wd&3;
            long gb = (long)(col0+r)*ldb + k0 + (wi<<3);
            pBh[i] = *(const uint4*)(Bh+gb);
            pBl[i] = *(const uint4*)(Bl+gb);
        }
    }

    for(int kc=0; kc<nch; kc++){
        // store prefetched chunk to smem
        #pragma unroll
        for(int i=0;i<2;i++){
            int wd = tid + (i<<8); int r = wd>>2, wi = wd&3;
            int so = r*40 + (wi<<3);
            *(uint4*)&sA_h[so] = pAh[i];
            *(uint4*)&sA_l[so] = pAl[i];
        }
        #pragma unroll
        for(int i=0;i<BW;i++){
            int wd = tid + (i<<8); int r = wd>>2, wi = wd&3;
            int so = r*40 + (wi<<3);
            *(uint4*)&sB_h[so] = pBh[i];
            *(uint4*)&sB_l[so] = pBl[i];
        }
        __syncthreads();
        // prefetch next chunk (overlaps with compute below)
        if(kc+1 < nch){
            int k0 = (kc+1)<<5;
            #pragma unroll
            for(int i=0;i<2;i++){
                int wd = tid + (i<<8); int r = wd>>2, wi = wd&3;
                long ga = (long)(row0+r)*lda + k0 + (wi<<3);
                pAh[i] = *(const uint4*)(Ah+ga);
                pAl[i] = *(const uint4*)(Al+ga);
            }
            #pragma unroll
            for(int i=0;i<BW;i++){
                int wd = tid + (i<<8); int r = wd>>2, wi = wd&3;
                long gb = (long)(col0+r)*ldb + k0 + (wi<<3);
                pBh[i] = *(const uint4*)(Bh+gb);
                pBl[i] = *(const uint4*)(Bl+gb);
            }
        }
        // compute: 2 k16 steps
        #pragma unroll
        for(int ks=0; ks<2; ks++){
            uint32_t bh[NT][2], bl[NT][2];
            #pragma unroll
            for(int j=0;j<NT;j++){
                int br = wn*(BN/4) + j*8 + gid;
                int bc = ks*16 + t4*2;
                bh[j][0] = *(const uint32_t*)&sB_h[br*40+bc];
                bh[j][1] = *(const uint32_t*)&sB_h[br*40+bc+8];
                bl[j][0] = *(const uint32_t*)&sB_l[br*40+bc];
                bl[j][1] = *(const uint32_t*)&sB_l[br*40+bc+8];
            }
            #pragma unroll
            for(int mt=0;mt<4;mt++){
                int ar = wm*64 + mt*16 + gid;
                int ac = ks*16 + t4*2;
                uint32_t ah[4], al[4];
                ah[0] = *(const uint32_t*)&sA_h[ar*40+ac];
                ah[1] = *(const uint32_t*)&sA_h[(ar+8)*40+ac];
                ah[2] = *(const uint32_t*)&sA_h[ar*40+ac+8];
                ah[3] = *(const uint32_t*)&sA_h[(ar+8)*40+ac+8];
                al[0] = *(const uint32_t*)&sA_l[ar*40+ac];
                al[1] = *(const uint32_t*)&sA_l[(ar+8)*40+ac];
                al[2] = *(const uint32_t*)&sA_l[ar*40+ac+8];
                al[3] = *(const uint32_t*)&sA_l[(ar+8)*40+ac+8];
                #pragma unroll
                for(int j=0;j<NT;j++){
                    mma_bf(cc[mt][j], ah, bh[j]);
                    mma_bf(cc[mt][j], ah, bl[j]);
                    mma_bf(cc[mt][j], al, bh[j]);
                }
            }
        }
        __syncthreads();
    }

    // epilogue
    #pragma unroll
    for(int mt=0;mt<4;mt++){
        #pragma unroll
        for(int j=0;j<NT;j++){
            int gn = col0 + wn*(BN/4) + j*8 + t4*2;
            #pragma unroll
            for(int h=0;h<2;h++){
                int gm = row0 + wm*64 + mt*16 + gid + 8*h;
                long cr = (long)gm*ldc + coff + gn;
                float v0 = cc[mt][j][2*h+0]*alpha;
                float v1 = cc[mt][j][2*h+1]*alpha;
                if(biasMode==1){ v0 += bias[gn]; v1 += bias[gn+1]; }
                else if(biasMode==2){ float bb = bias[gm]; v0 += bb; v1 += bb; }
                if(Res){ float2 rr = *(const float2*)(Res+cr); v0 += rr.x; v1 += rr.y; }
                if(Cf){ float2 o; o.x=v0; o.y=v1; *(float2*)(Cf+cr) = o; }
                if(Ch){
                    __nv_bfloat162 hp, lp;
                    hp.x = __float2bfloat16(v0); hp.y = __float2bfloat16(v1);
                    lp.x = __float2bfloat16(v0 - __bfloat162float(hp.x));
                    lp.y = __float2bfloat16(v1 - __bfloat162float(hp.y));
                    *(__nv_bfloat162*)(Ch+cr) = hp;
                    *(__nv_bfloat162*)(Cl+cr) = lp;
                }
            }
        }
    }
}

// ---------------- host ----------------
static void ltc(const bf* Ah, const bf* Al, const bf* Bh, const bf* Bl,
                const float* bias, int bMode, const float* Res,
                float* Cf, bf* Ch, bf* Cl,
                int M, int N, int K, int lda, int ldb, int ldc, int nTile,
                int Z, int Hn, long sAb, long sAh, long sBb, long sBh, long sCb, long sCh,
                float alpha)
{
    if(nTile == 128){
        int smem = (2*5120 + 2*128*40) * 2;   // 40960 B
        dim3 g(N/128, M/128, Z);
        gemm_mma<128><<<g, 256, smem>>>(Ah,Al,Bh,Bl,bias,bMode,Res,Cf,Ch,Cl,
                                        K,lda,ldb,ldc,Hn,sAb,sAh,sBb,sBh,sCb,sCh,alpha);
    } else {
        int smem = (2*5120 + 2*64*40) * 2;    // 30720 B
        dim3 g(N/64, M/128, Z);
        gemm_mma<64><<<g, 256, smem>>>(Ah,Al,Bh,Bl,bias,bMode,Res,Cf,Ch,Cl,
                                       K,lda,ldb,ldc,Hn,sAb,sAh,sBb,sBh,sCb,sCh,alpha);
    }
}
#define SYM(T,v,s) T* v; { void* p_; cudaGetSymbolAddress(&p_, s); v = (T*)p_; }

extern "C" void kernel_launch(void* const* d_in, const int* in_sizes, int n_in,
                              void* d_out, int out_size)
{
    (void)in_sizes; (void)n_in; (void)out_size;
    const float* spatial   = (const float*)d_in[0];
    const float* temporal  = (const float*)d_in[1];
    const float* sLqg=(const float*)d_in[2],  *sLqb=(const float*)d_in[3];
    const float* sLkg=(const float*)d_in[4],  *sLkb=(const float*)d_in[5];
    const float* sWqkv=(const float*)d_in[6], *sBqkv=(const float*)d_in[7];
    const float* sWo=(const float*)d_in[8],   *sBo=(const float*)d_in[9];
    const float* sWp=(const float*)d_in[10],  *sBp=(const float*)d_in[11];
    const float* tLqg=(const float*)d_in[12], *tLqb=(const float*)d_in[13];
    const float* tLkg=(const float*)d_in[14], *tLkb=(const float*)d_in[15];
    const float* tWqkv=(const float*)d_in[16],*tBqkv=(const float*)d_in[17];
    const float* tWo=(const float*)d_in[18],  *tBo=(const float*)d_in[19];
    const float* tWp=(const float*)d_in[20],  *tBp=(const float*)d_in[21];
    const float* mLg=(const float*)d_in[22],  *mLb=(const float*)d_in[23];
    const float* mWin=(const float*)d_in[24], *mBin=(const float*)d_in[25];
    const float* mWout=(const float*)d_in[26],*mBout=(const float*)d_in[27];
    float* out = (float*)d_out;

    SYM(bf,lsqh,LsQh) SYM(bf,lsql,LsQl) SYM(bf,ltkh,LtKVh) SYM(bf,ltkl,LtKVl)
    SYM(bf,ltqh,LtQh) SYM(bf,ltql,LtQl) SYM(bf,lskh,LsKVh) SYM(bf,lskl,LsKVl)
    SYM(bf,qsh,Qsh) SYM(bf,qsl,Qsl) SYM(bf,ksh,Ksh) SYM(bf,ksl,Ksl)
    SYM(bf,vsh,VtSh) SYM(bf,vsl,VtSl) SYM(bf,qth,Qth) SYM(bf,qtl,Qtl)
    SYM(bf,kth,Kth) SYM(bf,ktl,Ktl) SYM(bf,vth,VtTh) SYM(bf,vtl,VtTl)
    SYM(float,sc,Sc) SYM(bf,pph,Pph) SYM(bf,ppl,Ppl)
    SYM(bf,ash,AtSh) SYM(bf,asl,AtSl) SYM(bf,ath,AtTh) SYM(bf,atl,AtTl)
    SYM(bf,h1sh,H1Sh) SYM(bf,h1sl,H1Sl) SYM(bf,h1th,H1Th) SYM(bf,h1tl,H1Tl)
    SYM(float,sctx,SctxF) SYM(float,tctx,TctxF) SYM(float,tmn,TmeanF)
    SYM(bf,hmh,Hmh) SYM(bf,hml,Hml) SYM(float,uv,UvF)
    SYM(bf,gth,Gth) SYM(bf,gtl,Gtl)
    SYM(bf,wqsh,WqkvSh) SYM(bf,wqsl,WqkvSl) SYM(bf,wqth,WqkvTh) SYM(bf,wqtl,WqkvTl)
    SYM(bf,wosh,WoSh) SYM(bf,wosl,WoSl) SYM(bf,wpsh,WpSh) SYM(bf,wpsl,WpSl)
    SYM(bf,woth,WoTh) SYM(bf,wotl,WoTl) SYM(bf,wpth,WpTh) SYM(bf,wptl,WpTl)
    SYM(bf,winh,Winh) SYM(bf,winl,Winl) SYM(bf,wouth,Wouth) SYM(bf,woutl,Woutl)
    SYM(float,binp,BinP)

    #define CV(src,dh,dl,dR,dC,sR,sC) conv_k<<<(int)(((long)(dR)*(dC)+255)/256),256>>>(src,dh,dl,dR,dC,sR,sC)
    CV(sWqkv,wqsh,wqsl,3*KD,KD,3*KD,KD);
    CV(tWqkv,wqth,wqtl,3*KD,KD,3*KD,KD);
    CV(sWo,wosh,wosl,KD,KD,KD,KD);   CV(sWp,wpsh,wpsl,KD,KD,KD,KD);
    CV(tWo,woth,wotl,KD,KD,KD,KD);   CV(tWp,wpth,wptl,KD,KD,KD,KD);
    CV(mWin,winh,winl,NPAD,2*KD,2*KHID,2*KD);
    CV(mWout,wouth,woutl,KD,KPAD,KD,KHID);
    padc_k<<<(NPAD+255)/256,256>>>(mBin,binp,2*KHID,NPAD);

    ln_k<<<SROWS,128>>>(spatial, sLqg,sLqb, lsqh,lsql);
    ln_k<<<TROWS,128>>>(temporal,sLkg,sLkb, ltkh,ltkl);
    ln_k<<<TROWS,128>>>(temporal,tLqg,tLqb, ltqh,ltql);
    ln_k<<<SROWS,128>>>(spatial, tLkg,tLkb, lskh,lskl);

    // projections
    ltc(lsqh,lsql, wqsh,wqsl, sBqkv,1,0, 0,qsh,qsl, SROWS,KD,KD, KD,KD,KD,128, 1,1,0,0,0,0,0,0, 1.f);
    ltc(ltkh,ltkl, wqsh+KD*KD,wqsl+KD*KD, sBqkv+KD,1,0, 0,ksh,ksl, TROWS,KD,KD, KD,KD,KD,128, 1,1,0,0,0,0,0,0, 1.f);
    ltc(wqsh+2*KD*KD,wqsl+2*KD*KD, ltkh,ltkl, sBqkv+2*KD,2,0, 0,vsh,vsl, KD,KNT,KD, KD,KD,KNT,128,
        KB,1, 0,0, (long)KNT*KD,0, (long)KD*KNT,0, 1.f);
    ltc(ltqh,ltql, wqth,wqtl, tBqkv,1,0, 0,qth,qtl, TROWS,KD,KD, KD,KD,KD,128, 1,1,0,0,0,0,0,0, 1.f);
    ltc(lskh,lskl, wqth+KD*KD,wqtl+KD*KD, tBqkv+KD,1,0, 0,kth,ktl, SROWS,KD,KD, KD,KD,KD,128, 1,1,0,0,0,0,0,0, 1.f);
    ltc(wqth+2*KD*KD,wqtl+2*KD*KD, lskh,lskl, tBqkv+2*KD,2,0, 0,vth,vtl, KD,KNS,KD, KD,KD,KNS,128,
        KB,1, 0,0, (long)KNS*KD,0, (long)KD*KNS,0, 1.f);

    // spatial attention
    ltc(qsh,qsl, ksh,ksl, 0,0,0, sc,0,0, KNS,KNT,KDH, KD,KD,KNT,128,
        KB*KH,KH, (long)KNS*KD,KDH, (long)KNT*KD,KDH, (long)KH*KNS*KNT,(long)KNS*KNT, 0.125f);
    sm_k<2><<<KB*KH*KNS,256>>>(sc, pph, ppl);
    ltc(pph,ppl, vsh,vsl, 0,0,0, 0,ash,asl, KNS,KDH,KNT, KNT,KNT,KD,64,
        KB*KH,KH, (long)KH*KNS*KNT,(long)KNS*KNT, (long)KD*KNT,(long)KDH*KNT, (long)KNS*KD,KDH, 1.f);
    ltc(ash,asl, wosh,wosl, sBo,1,0, 0,h1sh,h1sl, SROWS,KD,KD, KD,KD,KD,128, 1,1,0,0,0,0,0,0, 1.f);
    ltc(h1sh,h1sl, wpsh,wpsl, sBp,1,spatial, sctx,0,0, SROWS,KD,KD, KD,KD,KD,128, 1,1,0,0,0,0,0,0, 1.f);

    // temporal attention
    ltc(qth,qtl, kth,ktl, 0,0,0, sc,0,0, KNT,KNS,KDH, KD,KD,KNS,128,
        KB*KH,KH, (long)KNT*KD,KDH, (long)KNS*KD,KDH, (long)KH*KNT*KNS,(long)KNT*KNS, 0.125f);
    sm_k<16><<<KB*KH*KNT,256>>>(sc, pph, ppl);
    ltc(pph,ppl, vth,vtl, 0,0,0, 0,ath,atl, KNT,KDH,KNS, KNS,KNS,KD,64,
        KB*KH,KH, (long)KH*KNT*KNS,(long)KNT*KNS, (long)KD*KNS,(long)KDH*KNS, (long)KNT*KD,KDH, 1.f);
    ltc(ath,atl, woth,wotl, tBo,1,0, 0,h1th,h1tl, TROWS,KD,KD, KD,KD,KD,128, 1,1,0,0,0,0,0,0, 1.f);
    ltc(h1th,h1tl, wpth,wptl, tBp,1,temporal, tctx,0,0, TROWS,KD,KD, KD,KD,KD,128, 1,1,0,0,0,0,0,0, 1.f);

    // mix
    tmean_k<<<(KB*KD+127)/128,128>>>(tctx, tmn);
    mixln_k<<<SROWS,128>>>(sctx, tmn, mLg, mLb, hmh, hml);
    ltc(hmh,hml, winh,winl, binp,1,0, uv,0,0, SROWS,NPAD,2*KD, 2*KD,2*KD,NPAD,128, 1,1,0,0,0,0,0,0, 1.f);
    { long tot = (long)SROWS*KPAD; gate_k<<<(int)((tot+255)/256),256>>>(uv, gth, gtl); }
    ltc(gth,gtl, wouth,woutl, mBout,1,sctx, out,0,0, SROWS,KD,KPAD, KPAD,KPAD,KD,128, 1,1,0,0,0,0,0,0, 1.f);
}

// round 6
// speedup vs baseline: 2.9854x; 1.2525x over previous
#include <cuda_runtime.h>
#include <cuda_bf16.h>
#include <math.h>
#include <stdint.h>

#define KD    512
#define KH    8
#define KDH   64
#define KHID  2730
#define KB    4
#define KNS   4096
#define KNT   512
#define SROWS (KB*KNS)
#define TROWS (KB*KNT)
#define KPAD  2752
#define NPAD  5504

typedef __nv_bfloat16 bf;
#define DEVB(n, s) __device__ __align__(16) bf n[s]
#define DEVF(n, s) __device__ __align__(16) float n[s]

// activations / intermediates
DEVB(LsQh,SROWS*KD); DEVB(LsQl,SROWS*KD);
DEVB(LtKVh,TROWS*KD);DEVB(LtKVl,TROWS*KD);
DEVB(LtQh,TROWS*KD); DEVB(LtQl,TROWS*KD);
DEVB(LsKVh,SROWS*KD);DEVB(LsKVl,SROWS*KD);
DEVB(Qsh,SROWS*KD);  DEVB(Qsl,SROWS*KD);
DEVB(Ksh,TROWS*KD);  DEVB(Ksl,TROWS*KD);
DEVB(VtSh,KB*KD*KNT);DEVB(VtSl,KB*KD*KNT);
DEVB(Qth,TROWS*KD);  DEVB(Qtl,TROWS*KD);
DEVB(Kth,SROWS*KD);  DEVB(Ktl,SROWS*KD);
DEVB(VtTh,KB*KD*KNS);DEVB(VtTl,KB*KD*KNS);
DEVF(Sc,(size_t)KB*KH*KNS*KNT);
DEVB(Pph,(size_t)KB*KH*KNS*KNT); DEVB(Ppl,(size_t)KB*KH*KNS*KNT);
DEVB(AtSh,SROWS*KD); DEVB(AtSl,SROWS*KD);
DEVB(AtTh,TROWS*KD); DEVB(AtTl,TROWS*KD);
DEVB(H1Sh,SROWS*KD); DEVB(H1Sl,SROWS*KD);
DEVB(H1Th,TROWS*KD); DEVB(H1Tl,TROWS*KD);
DEVF(SctxF,SROWS*KD);
DEVF(TctxF,TROWS*KD);
DEVF(TmeanF,KB*KD);
DEVB(Hmh,SROWS*2*KD); DEVB(Hml,SROWS*2*KD);
DEVF(UvF,(size_t)SROWS*NPAD);
DEVB(Gth,(size_t)SROWS*KPAD); DEVB(Gtl,(size_t)SROWS*KPAD);
// weights
DEVB(WqkvSh,3*KD*KD); DEVB(WqkvSl,3*KD*KD);
DEVB(WqkvTh,3*KD*KD); DEVB(WqkvTl,3*KD*KD);
DEVB(WoSh,KD*KD); DEVB(WoSl,KD*KD);
DEVB(WpSh,KD*KD); DEVB(WpSl,KD*KD);
DEVB(WoTh,KD*KD); DEVB(WoTl,KD*KD);
DEVB(WpTh,KD*KD); DEVB(WpTl,KD*KD);
DEVB(Winh,NPAD*2*KD); DEVB(Winl,NPAD*2*KD);
DEVB(Wouth,KD*KPAD);  DEVB(Woutl,KD*KPAD);
DEVF(BinP,NPAD);

__device__ __forceinline__ void splitw(float x, bf* H, bf* L){
    bf h = __float2bfloat16(x); *H = h; *L = __float2bfloat16(x - __bfloat162float(h));
}

__device__ __forceinline__ void mma_bf(float* c, const uint32_t* a, const uint32_t* b){
    asm volatile("mma.sync.aligned.m16n8k16.row.col.f32.bf16.bf16.f32 "
        "{%0,%1,%2,%3}, {%4,%5,%6,%7}, {%8,%9}, {%0,%1,%2,%3};"
        : "+f"(c[0]),"+f"(c[1]),"+f"(c[2]),"+f"(c[3])
        : "r"(a[0]),"r"(a[1]),"r"(a[2]),"r"(a[3]), "r"(b[0]),"r"(b[1]));
}
__device__ __forceinline__ uint32_t cvsm(const void* p){
    uint32_t a; asm("{ .reg .u64 t; cvta.to.shared.u64 t, %1; cvt.u32.u64 %0, t; }":"=r"(a):"l"(p)); return a;
}
__device__ __forceinline__ void ldm_x4(uint32_t* r, uint32_t a){
    asm volatile("ldmatrix.sync.aligned.m8n8.x4.shared.b16 {%0,%1,%2,%3}, [%4];"
        : "=r"(r[0]),"=r"(r[1]),"=r"(r[2]),"=r"(r[3]) : "r"(a));
}
#define CPA(d, s) asm volatile("cp.async.cg.shared.global [%0], [%1], 16;"::"r"(d),"l"(s):"memory")
#define CPA_COMMIT() asm volatile("cp.async.commit_group;":::"memory")
#define CPA_WAIT1() asm volatile("cp.async.wait_group 1;":::"memory")
#define CPA_WAIT0() asm volatile("cp.async.wait_group 0;":::"memory")

// ---------------- reductions ----------------
__device__ __forceinline__ float brSum(float v){
    __shared__ float sh[33]; __syncthreads();
    int ln = threadIdx.x&31, w = threadIdx.x>>5;
    #pragma unroll
    for(int o=16;o;o>>=1) v += __shfl_xor_sync(~0u,v,o);
    if(!ln) sh[w]=v; __syncthreads();
    if(!w){ int nw=blockDim.x>>5; float r=(ln<nw)?sh[ln]:0.f;
        #pragma unroll
        for(int o=16;o;o>>=1) r += __shfl_xor_sync(~0u,r,o);
        if(!ln) sh[32]=r; }
    __syncthreads(); return sh[32];
}
__device__ __forceinline__ float brMax(float v){
    __shared__ float sh[33]; __syncthreads();
    int ln = threadIdx.x&31, w = threadIdx.x>>5;
    #pragma unroll
    for(int o=16;o;o>>=1) v = fmaxf(v,__shfl_xor_sync(~0u,v,o));
    if(!ln) sh[w]=v; __syncthreads();
    if(!w){ int nw=blockDim.x>>5; float r=(ln<nw)?sh[ln]:-1e30f;
        #pragma unroll
        for(int o=16;o;o>>=1) r = fmaxf(r,__shfl_xor_sync(~0u,r,o));
        if(!ln) sh[32]=r; }
    __syncthreads(); return sh[32];
}

// ---------------- elementwise kernels ----------------
__global__ void __launch_bounds__(128)
ln_k(const float* __restrict__ x, const float* __restrict__ g, const float* __restrict__ b,
     bf* __restrict__ yh, bf* __restrict__ yl)
{
    long row = blockIdx.x;
    const float* px = x + row*KD;
    bf *ph = yh + row*KD, *pl = yl + row*KD;
    int t = threadIdx.x;
    float v[4]; float s=0.f;
    #pragma unroll
    for(int i=0;i<4;i++){ v[i]=px[t+(i<<7)]; s+=v[i]; }
    s = brSum(s); float m = s*(1.f/KD);
    float q=0.f;
    #pragma unroll
    for(int i=0;i<4;i++){ float d=v[i]-m; q+=d*d; }
    q = brSum(q); float inv = rsqrtf(q*(1.f/KD)+1e-5f);
    #pragma unroll
    for(int i=0;i<4;i++){ int c=t+(i<<7); splitw((v[i]-m)*inv*g[c]+b[c], ph+c, pl+c); }
}

__global__ void __launch_bounds__(128)
mixln_k(const float* __restrict__ sc, const float* __restrict__ tm,
        const float* __restrict__ g, const float* __restrict__ b,
        bf* __restrict__ yh, bf* __restrict__ yl)
{
    int row = blockIdx.x, bb = row>>12;
    const float *ps = sc + (long)row*KD, *pm = tm + (long)bb*KD;
    bf *ph = yh + (long)row*2*KD, *pl = yl + (long)row*2*KD;
    int t = threadIdx.x;
    float v[8]; float s=0.f;
    #pragma unroll
    for(int i=0;i<8;i++){ int c=t+(i<<7); v[i]=(c<KD)?ps[c]:pm[c-KD]; s+=v[i]; }
    s = brSum(s); float m = s*(1.f/1024.f);
    float q=0.f;
    #pragma unroll
    for(int i=0;i<8;i++){ float d=v[i]-m; q+=d*d; }
    q = brSum(q); float inv = rsqrtf(q*(1.f/1024.f)+1e-5f);
    #pragma unroll
    for(int i=0;i<8;i++){ int c=t+(i<<7); splitw((v[i]-m)*inv*g[c]+b[c], ph+c, pl+c); }
}

template<int NV>
__global__ void __launch_bounds__(256)
sm_k(const float* __restrict__ S, bf* __restrict__ Ph, bf* __restrict__ Pl)
{
    long row = blockIdx.x;
    const int cols = NV*256;
    const float* p = S + row*(long)cols;
    bf *ph = Ph + row*(long)cols, *pl = Pl + row*(long)cols;
    int t = threadIdx.x;
    float v[NV]; float mx=-1e30f;
    #pragma unroll
    for(int i=0;i<NV;i++){ v[i]=p[t+(i<<8)]; mx=fmaxf(mx,v[i]); }
    mx = brMax(mx);
    float s=0.f;
    #pragma unroll
    for(int i=0;i<NV;i++){ v[i]=__expf(v[i]-mx); s+=v[i]; }
    s = brSum(s); float inv = 1.f/s;
    #pragma unroll
    for(int i=0;i<NV;i++){ int c=t+(i<<8); splitw(v[i]*inv, ph+c, pl+c); }
}

__global__ void tmean_k(const float* __restrict__ tc, float* __restrict__ o)
{
    int i = blockIdx.x*blockDim.x + threadIdx.x;
    if(i >= KB*KD) return;
    int bb=i>>9, dd=i&511;
    const float* p = tc + (long)bb*KNT*KD + dd;
    float s=0.f;
    for(int t=0;t<KNT;t++) s += p[t*KD];
    o[i] = s*(1.f/KNT);
}

__global__ void gate_k(const float* __restrict__ uv, bf* __restrict__ gh, bf* __restrict__ gl)
{
    long i = (long)blockIdx.x*blockDim.x + threadIdx.x;
    if(i >= (long)SROWS*KPAD) return;
    long r = i/KPAD; int c = (int)(i - r*KPAD);
    float val = 0.f;
    if(c < KHID){
        float u = uv[r*NPAD + c], vv = uv[r*NPAD + KHID + c];
        val = (u/(1.f+__expf(-u)))*vv;
    }
    splitw(val, gh+i, gl+i);
}

__global__ void conv_k(const float* __restrict__ s, bf* __restrict__ dh, bf* __restrict__ dl,
                       int dR, int dC, int sR, int sC)
{
    long i = (long)blockIdx.x*blockDim.x + threadIdx.x;
    if(i >= (long)dR*dC) return;
    int r = (int)(i/dC), c = (int)(i - (long)r*dC);
    float v = (r<sR && c<sC) ? s[(long)r*sC + c] : 0.f;
    splitw(v, dh+i, dl+i);
}

__global__ void padc_k(const float* __restrict__ s, float* __restrict__ d, int ns, int nd)
{
    int i = blockIdx.x*blockDim.x + threadIdx.x;
    if(i<nd) d[i] = (i<ns)?s[i]:0.f;
}

// ---------------- split-bf16 HMMA GEMM (NT), ldmatrix + cp.async 2-stage ----
// C[m,n] = alpha*sum_k A[m,k]*B[n,k] (+bias)(+Res). M%128==0, N%BN==0, K%32==0.
// 256 threads, 8 warps 2(M)x4(N). smem rows padded to 40 bf16 (80B) — this
// stride is conflict-free for both the 16B cp.async stores and ldmatrix.
template<int BN>
__global__ void __launch_bounds__(256)
gemm_mma(const bf* __restrict__ Ah, const bf* __restrict__ Al,
         const bf* __restrict__ Bh, const bf* __restrict__ Bl,
         const float* __restrict__ bias, int biasMode, const float* __restrict__ Res,
         float* __restrict__ Cf, bf* __restrict__ Ch, bf* __restrict__ Cl,
         int K, int lda, int ldb, int ldc,
         int Hn, long sAb, long sAh2, long sBb, long sBh2, long sCb, long sCh2,
         float alpha)
{
    extern __shared__ char smem[];
    const int tid = threadIdx.x, lane = tid&31, w = tid>>5;
    const int wm = w&1, wn = w>>1;
    const int gid = lane>>2, t4 = lane&3;
    constexpr int NT = BN/32;           // n8 tiles per warp
    constexpr int BW = BN/64;           // B 16B words per thread per split
    constexpr int SS = 20480 + BN*160;  // bytes per pipeline stage

    int z = blockIdx.z, zb = z/Hn, zh = z - zb*Hn;
    long coff = (long)zb*sCb + (long)zh*sCh2;
    Ah += (long)zb*sAb + (long)zh*sAh2; Al += (long)zb*sAb + (long)zh*sAh2;
    Bh += (long)zb*sBb + (long)zh*sBh2; Bl += (long)zb*sBb + (long)zh*sBh2;

    const int row0 = blockIdx.y << 7;
    const int col0 = blockIdx.x * BN;
    uint32_t sb = cvsm(smem);
    int nch = K >> 5;

    float cc[4][NT][4];
    #pragma unroll
    for(int i=0;i<4;i++)
        #pragma unroll
        for(int j=0;j<NT;j++)
            #pragma unroll
            for(int q=0;q<4;q++) cc[i][j][q]=0.f;

    // async-load one K=32 stage
    auto issue = [&](int kc){
        uint32_t bufb = sb + (uint32_t)(kc&1)*SS;
        int k0 = kc<<5;
        #pragma unroll
        for(int i=0;i<2;i++){
            int wd = tid + (i<<8); int r = wd>>2, wi = wd&3;
            uint32_t so = bufb + (uint32_t)(r*80 + wi*16);
            long go = (long)(row0+r)*lda + k0 + (wi<<3);
            CPA(so,         Ah+go);
            CPA(so + 10240, Al+go);
        }
        #pragma unroll
        for(int i=0;i<BW;i++){
            int wd = tid + (i<<8); int r = wd>>2, wi = wd&3;
            uint32_t so = bufb + 20480u + (uint32_t)(r*80 + wi*16);
            long go = (long)(col0+r)*ldb + k0 + (wi<<3);
            CPA(so,           Bh+go);
            CPA(so + BN*80u,  Bl+go);
        }
        CPA_COMMIT();
    };

    issue(0);
    for(int kc=0; kc<nch; kc++){
        if(kc+1 < nch){ issue(kc+1); CPA_WAIT1(); }
        else          { CPA_WAIT0(); }
        __syncthreads();
        uint32_t bufb = sb + (uint32_t)(kc&1)*SS;
        #pragma unroll
        for(int ks=0; ks<2; ks++){
            uint32_t bh[NT][2], bl[NT][2];
            #pragma unroll
            for(int jp=0; jp<NT/2; jp++){
                int nr = wn*(BN/4) + jp*16 + (lane&7) + (((lane>>4)&1)<<3);
                uint32_t cb = (uint32_t)(((lane>>3)&1)<<4);
                uint32_t ad = bufb + 20480u + (uint32_t)(nr*80) + (uint32_t)(ks*32) + cb;
                ldm_x4(&bh[2*jp][0], ad);
                ldm_x4(&bl[2*jp][0], ad + BN*80u);
            }
            #pragma unroll
            for(int mt=0; mt<4; mt++){
                int ar = wm*64 + mt*16 + (lane&15);
                uint32_t cb = (uint32_t)(((lane>>4)&1)<<4);
                uint32_t ad = bufb + (uint32_t)(ar*80) + (uint32_t)(ks*32) + cb;
                uint32_t ah[4], al[4];
                ldm_x4(ah, ad);
                ldm_x4(al, ad + 10240u);
                #pragma unroll
                for(int j=0; j<NT; j++){
                    mma_bf(cc[mt][j], ah, bh[j]);
                    mma_bf(cc[mt][j], ah, bl[j]);
                    mma_bf(cc[mt][j], al, bh[j]);
                }
            }
        }
        __syncthreads();
    }

    // epilogue
    #pragma unroll
    for(int mt=0;mt<4;mt++){
        #pragma unroll
        for(int j=0;j<NT;j++){
            int gn = col0 + wn*(BN/4) + j*8 + t4*2;
            #pragma unroll
            for(int h=0;h<2;h++){
                int gm = row0 + wm*64 + mt*16 + gid + 8*h;
                long cr = (long)gm*ldc + coff + gn;
                float v0 = cc[mt][j][2*h+0]*alpha;
                float v1 = cc[mt][j][2*h+1]*alpha;
                if(biasMode==1){ v0 += bias[gn]; v1 += bias[gn+1]; }
                else if(biasMode==2){ float bb = bias[gm]; v0 += bb; v1 += bb; }
                if(Res){ float2 rr = *(const float2*)(Res+cr); v0 += rr.x; v1 += rr.y; }
                if(Cf){ float2 o; o.x=v0; o.y=v1; *(float2*)(Cf+cr) = o; }
                if(Ch){
                    __nv_bfloat162 hp, lp;
                    hp.x = __float2bfloat16(v0); hp.y = __float2bfloat16(v1);
                    lp.x = __float2bfloat16(v0 - __bfloat162float(hp.x));
                    lp.y = __float2bfloat16(v1 - __bfloat162float(hp.y));
                    *(__nv_bfloat162*)(Ch+cr) = hp;
                    *(__nv_bfloat162*)(Cl+cr) = lp;
                }
            }
        }
    }
}

// ---------------- host ----------------
static void ltc(const bf* Ah, const bf* Al, const bf* Bh, const bf* Bl,
                const float* bias, int bMode, const float* Res,
                float* Cf, bf* Ch, bf* Cl,
                int M, int N, int K, int lda, int ldb, int ldc, int nTile,
                int Z, int Hn, long sAb, long sAh, long sBb, long sBh, long sCb, long sCh,
                float alpha)
{
    if(nTile == 128){
        int smem = 2*(20480 + 128*160);   // 81920 B
        cudaFuncSetAttribute(gemm_mma<128>, cudaFuncAttributeMaxDynamicSharedMemorySize, smem);
        dim3 g(N/128, M/128, Z);
        gemm_mma<128><<<g, 256, smem>>>(Ah,Al,Bh,Bl,bias,bMode,Res,Cf,Ch,Cl,
                                        K,lda,ldb,ldc,Hn,sAb,sAh,sBb,sBh,sCb,sCh,alpha);
    } else {
        int smem = 2*(20480 + 64*160);    // 61440 B
        cudaFuncSetAttribute(gemm_mma<64>, cudaFuncAttributeMaxDynamicSharedMemorySize, smem);
        dim3 g(N/64, M/128, Z);
        gemm_mma<64><<<g, 256, smem>>>(Ah,Al,Bh,Bl,bias,bMode,Res,Cf,Ch,Cl,
                                       K,lda,ldb,ldc,Hn,sAb,sAh,sBb,sBh,sCb,sCh,alpha);
    }
}
#define SYM(T,v,s) T* v; { void* p_; cudaGetSymbolAddress(&p_, s); v = (T*)p_; }

extern "C" void kernel_launch(void* const* d_in, const int* in_sizes, int n_in,
                              void* d_out, int out_size)
{
    (void)in_sizes; (void)n_in; (void)out_size;
    const float* spatial   = (const float*)d_in[0];
    const float* temporal  = (const float*)d_in[1];
    const float* sLqg=(const float*)d_in[2],  *sLqb=(const float*)d_in[3];
    const float* sLkg=(const float*)d_in[4],  *sLkb=(const float*)d_in[5];
    const float* sWqkv=(const float*)d_in[6], *sBqkv=(const float*)d_in[7];
    const float* sWo=(const float*)d_in[8],   *sBo=(const float*)d_in[9];
    const float* sWp=(const float*)d_in[10],  *sBp=(const float*)d_in[11];
    const float* tLqg=(const float*)d_in[12], *tLqb=(const float*)d_in[13];
    const float* tLkg=(const float*)d_in[14], *tLkb=(const float*)d_in[15];
    const float* tWqkv=(const float*)d_in[16],*tBqkv=(const float*)d_in[17];
    const float* tWo=(const float*)d_in[18],  *tBo=(const float*)d_in[19];
    const float* tWp=(const float*)d_in[20],  *tBp=(const float*)d_in[21];
    const float* mLg=(const float*)d_in[22],  *mLb=(const float*)d_in[23];
    const float* mWin=(const float*)d_in[24], *mBin=(const float*)d_in[25];
    const float* mWout=(const float*)d_in[26],*mBout=(const float*)d_in[27];
    float* out = (float*)d_out;

    SYM(bf,lsqh,LsQh) SYM(bf,lsql,LsQl) SYM(bf,ltkh,LtKVh) SYM(bf,ltkl,LtKVl)
    SYM(bf,ltqh,LtQh) SYM(bf,ltql,LtQl) SYM(bf,lskh,LsKVh) SYM(bf,lskl,LsKVl)
    SYM(bf,qsh,Qsh) SYM(bf,qsl,Qsl) SYM(bf,ksh,Ksh) SYM(bf,ksl,Ksl)
    SYM(bf,vsh,VtSh) SYM(bf,vsl,VtSl) SYM(bf,qth,Qth) SYM(bf,qtl,Qtl)
    SYM(bf,kth,Kth) SYM(bf,ktl,Ktl) SYM(bf,vth,VtTh) SYM(bf,vtl,VtTl)
    SYM(float,sc,Sc) SYM(bf,pph,Pph) SYM(bf,ppl,Ppl)
    SYM(bf,ash,AtSh) SYM(bf,asl,AtSl) SYM(bf,ath,AtTh) SYM(bf,atl,AtTl)
    SYM(bf,h1sh,H1Sh) SYM(bf,h1sl,H1Sl) SYM(bf,h1th,H1Th) SYM(bf,h1tl,H1Tl)
    SYM(float,sctx,SctxF) SYM(float,tctx,TctxF) SYM(float,tmn,TmeanF)
    SYM(bf,hmh,Hmh) SYM(bf,hml,Hml) SYM(float,uv,UvF)
    SYM(bf,gth,Gth) SYM(bf,gtl,Gtl)
    SYM(bf,wqsh,WqkvSh) SYM(bf,wqsl,WqkvSl) SYM(bf,wqth,WqkvTh) SYM(bf,wqtl,WqkvTl)
    SYM(bf,wosh,WoSh) SYM(bf,wosl,WoSl) SYM(bf,wpsh,WpSh) SYM(bf,wpsl,WpSl)
    SYM(bf,woth,WoTh) SYM(bf,wotl,WoTl) SYM(bf,wpth,WpTh) SYM(bf,wptl,WpTl)
    SYM(bf,winh,Winh) SYM(bf,winl,Winl) SYM(bf,wouth,Wouth) SYM(bf,woutl,Woutl)
    SYM(float,binp,BinP)

    #define CV(src,dh,dl,dR,dC,sR,sC) conv_k<<<(int)(((long)(dR)*(dC)+255)/256),256>>>(src,dh,dl,dR,dC,sR,sC)
    CV(sWqkv,wqsh,wqsl,3*KD,KD,3*KD,KD);
    CV(tWqkv,wqth,wqtl,3*KD,KD,3*KD,KD);
    CV(sWo,wosh,wosl,KD,KD,KD,KD);   CV(sWp,wpsh,wpsl,KD,KD,KD,KD);
    CV(tWo,woth,wotl,KD,KD,KD,KD);   CV(tWp,wpth,wptl,KD,KD,KD,KD);
    CV(mWin,winh,winl,NPAD,2*KD,2*KHID,2*KD);
    CV(mWout,wouth,woutl,KD,KPAD,KD,KHID);
    padc_k<<<(NPAD+255)/256,256>>>(mBin,binp,2*KHID,NPAD);

    ln_k<<<SROWS,128>>>(spatial, sLqg,sLqb, lsqh,lsql);
    ln_k<<<TROWS,128>>>(temporal,sLkg,sLkb, ltkh,ltkl);
    ln_k<<<TROWS,128>>>(temporal,tLqg,tLqb, ltqh,ltql);
    ln_k<<<SROWS,128>>>(spatial, tLkg,tLkb, lskh,lskl);

    // projections
    ltc(lsqh,lsql, wqsh,wqsl, sBqkv,1,0, 0,qsh,qsl, SROWS,KD,KD, KD,KD,KD,128, 1,1,0,0,0,0,0,0, 1.f);
    ltc(ltkh,ltkl, wqsh+KD*KD,wqsl+KD*KD, sBqkv+KD,1,0, 0,ksh,ksl, TROWS,KD,KD, KD,KD,KD,128, 1,1,0,0,0,0,0,0, 1.f);
    ltc(wqsh+2*KD*KD,wqsl+2*KD*KD, ltkh,ltkl, sBqkv+2*KD,2,0, 0,vsh,vsl, KD,KNT,KD, KD,KD,KNT,128,
        KB,1, 0,0, (long)KNT*KD,0, (long)KD*KNT,0, 1.f);
    ltc(ltqh,ltql, wqth,wqtl, tBqkv,1,0, 0,qth,qtl, TROWS,KD,KD, KD,KD,KD,128, 1,1,0,0,0,0,0,0, 1.f);
    ltc(lskh,lskl, wqth+KD*KD,wqtl+KD*KD, tBqkv+KD,1,0, 0,kth,ktl, SROWS,KD,KD, KD,KD,KD,128, 1,1,0,0,0,0,0,0, 1.f);
    ltc(wqth+2*KD*KD,wqtl+2*KD*KD, lskh,lskl, tBqkv+2*KD,2,0, 0,vth,vtl, KD,KNS,KD, KD,KD,KNS,128,
        KB,1, 0,0, (long)KNS*KD,0, (long)KD*KNS,0, 1.f);

    // spatial attention
    ltc(qsh,qsl, ksh,ksl, 0,0,0, sc,0,0, KNS,KNT,KDH, KD,KD,KNT,128,
        KB*KH,KH, (long)KNS*KD,KDH, (long)KNT*KD,KDH, (long)KH*KNS*KNT,(long)KNS*KNT, 0.125f);
    sm_k<2><<<KB*KH*KNS,256>>>(sc, pph, ppl);
    ltc(pph,ppl, vsh,vsl, 0,0,0, 0,ash,asl, KNS,KDH,KNT, KNT,KNT,KD,64,
        KB*KH,KH, (long)KH*KNS*KNT,(long)KNS*KNT, (long)KD*KNT,(long)KDH*KNT, (long)KNS*KD,KDH, 1.f);
    ltc(ash,asl, wosh,wosl, sBo,1,0, 0,h1sh,h1sl, SROWS,KD,KD, KD,KD,KD,128, 1,1,0,0,0,0,0,0, 1.f);
    ltc(h1sh,h1sl, wpsh,wpsl, sBp,1,spatial, sctx,0,0, SROWS,KD,KD, KD,KD,KD,128, 1,1,0,0,0,0,0,0, 1.f);

    // temporal attention
    ltc(qth,qtl, kth,ktl, 0,0,0, sc,0,0, KNT,KNS,KDH, KD,KD,KNS,128,
        KB*KH,KH, (long)KNT*KD,KDH, (long)KNS*KD,KDH, (long)KH*KNT*KNS,(long)KNT*KNS, 0.125f);
    sm_k<16><<<KB*KH*KNT,256>>>(sc, pph, ppl);
    ltc(pph,ppl, vth,vtl, 0,0,0, 0,ath,atl, KNT,KDH,KNS, KNS,KNS,KD,64,
        KB*KH,KH, (long)KH*KNT*KNS,(long)KNT*KNS, (long)KD*KNS,(long)KDH*KNS, (long)KNT*KD,KDH, 1.f);
    ltc(ath,atl, woth,wotl, tBo,1,0, 0,h1th,h1tl, TROWS,KD,KD, KD,KD,KD,128, 1,1,0,0,0,0,0,0, 1.f);
    ltc(h1th,h1tl, wpth,wptl, tBp,1,temporal, tctx,0,0, TROWS,KD,KD, KD,KD,KD,128, 1,1,0,0,0,0,0,0, 1.f);

    // mix
    tmean_k<<<(KB*KD+127)/128,128>>>(tctx, tmn);
    mixln_k<<<SROWS,128>>>(sctx, tmn, mLg, mLb, hmh, hml);
    ltc(hmh,hml, winh,winl, binp,1,0, uv,0,0, SROWS,NPAD,2*KD, 2*KD,2*KD,NPAD,128, 1,1,0,0,0,0,0,0, 1.f);
    { long tot = (long)SROWS*KPAD; gate_k<<<(int)((tot+255)/256),256>>>(uv, gth, gtl); }
    ltc(gth,gtl, wouth,woutl, mBout,1,sctx, out,0,0, SROWS,KD,KPAD, KPAD,KPAD,KD,128, 1,1,0,0,0,0,0,0, 1.f);
}